// round 2
// baseline (speedup 1.0000x reference)
#include <cuda_runtime.h>

#define N_ROWS 2048      // 256 * 8
#define L 128
#define OUT 65
#define OUT2 (OUT * OUT) // 4225
#define EPS 1e-6f

__global__ __launch_bounds__(256) void gasf_kernel(const float* __restrict__ x,
                                                   float* __restrict__ out) {
    __shared__ unsigned ball[4];
    __shared__ float smn[4], smx[4];
    __shared__ float sc[OUT], ss[OUT];

    const int row = blockIdx.x;               // (n, c) flattened
    const int tid = threadIdx.x;
    const int lane = tid & 31;
    const int warp = tid >> 5;

    const float POS_INF = __int_as_float(0x7f800000);

    float v = 0.0f;
    if (tid < L) {
        v = x[row * L + tid];
        unsigned m = __ballot_sync(0xffffffffu, v != 0.0f);
        if (lane == 0) ball[warp] = m;
    }
    __syncthreads();

    // first/last nonzero position (all threads compute; cheap)
    int first = L, last = -1;
    {
        unsigned b0 = ball[0], b1 = ball[1], b2 = ball[2], b3 = ball[3];
        if (b0)      first = __ffs(b0) - 1;
        else if (b1) first = 32 + __ffs(b1) - 1;
        else if (b2) first = 64 + __ffs(b2) - 1;
        else if (b3) first = 96 + __ffs(b3) - 1;
        if (b3)      last = 96 + 31 - __clz(b3);
        else if (b2) last = 64 + 31 - __clz(b2);
        else if (b1) last = 32 + 31 - __clz(b1);
        else if (b0) last = 31 - __clz(b0);
    }

    bool valid = false;
    if (tid < L) {
        valid = (tid >= first) && (tid <= last);   // has_data implied by first<=last
        float mn = valid ? v : POS_INF;
        float mx = valid ? v : -POS_INF;
        #pragma unroll
        for (int off = 16; off; off >>= 1) {
            mn = fminf(mn, __shfl_xor_sync(0xffffffffu, mn, off));
            mx = fmaxf(mx, __shfl_xor_sync(0xffffffffu, mx, off));
        }
        if (lane == 0) { smn[warp] = mn; smx[warp] = mx; }
    }
    __syncthreads();

    float xmin = fminf(fminf(smn[0], smn[1]), fminf(smn[2], smn[3]));
    float xmax = fmaxf(fmaxf(smx[0], smx[1]), fmaxf(smx[2], smx[3]));
    // clamp + all-invalid handling collapse into fminf/fmaxf with 0 (inf -> 0)
    xmin = fminf(xmin, 0.0f);
    xmax = fmaxf(xmax, 0.0f);
    float range = fmaxf(xmax - xmin, EPS);

    if (tid < OUT) {
        float xn = valid ? (2.0f * (v - xmin) / range - 1.0f) : 0.0f;
        float c = fminf(fmaxf(xn, -1.0f + EPS), 1.0f - EPS);
        float s = sqrtf(fmaxf(1.0f - c * c, 0.0f));
        sc[tid] = c;
        ss[tid] = s;
    }
    __syncthreads();

    // write 65x65 tile: gasf[i][j] = c_i*c_j - s_i*s_j  (== cos(phi_i+phi_j))
    float* o = out + (size_t)row * OUT2;
    for (int idx = tid; idx < OUT2; idx += 256) {
        int i = idx / OUT;
        int j = idx - i * OUT;
        o[idx] = fmaf(sc[i], sc[j], -ss[i] * ss[j]);
    }
}

extern "C" void kernel_launch(void* const* d_in, const int* in_sizes, int n_in,
                              void* d_out, int out_size) {
    const float* x = (const float*)d_in[0];
    float* out = (float*)d_out;
    gasf_kernel<<<N_ROWS, 256>>>(x, out);
}

// round 3
// speedup vs baseline: 1.1797x; 1.1797x over previous
#include <cuda_runtime.h>

#define N_ROWS 2048      // 256 * 8
#define L 128
#define OUT 65
#define OUT2 (OUT * OUT) // 4225
#define EPS 1e-6f

__global__ __launch_bounds__(256) void gasf_kernel(const float* __restrict__ x,
                                                   float* __restrict__ out) {
    __shared__ unsigned ball[4];
    __shared__ float smn[4], smx[4];
    __shared__ float2 scss[OUT];   // (cos, sin) interleaved -> one LDS.64 per operand pair

    const int row = blockIdx.x;               // (n, c) flattened
    const int tid = threadIdx.x;
    const int lane = tid & 31;
    const int warp = tid >> 5;

    const float POS_INF = __int_as_float(0x7f800000);

    float v = 0.0f;
    if (tid < L) {
        v = x[row * L + tid];
        unsigned m = __ballot_sync(0xffffffffu, v != 0.0f);
        if (lane == 0) ball[warp] = m;
    }
    __syncthreads();

    // first/last nonzero position along L
    int first = L, last = -1;
    {
        unsigned b0 = ball[0], b1 = ball[1], b2 = ball[2], b3 = ball[3];
        if (b0)      first = __ffs(b0) - 1;
        else if (b1) first = 32 + __ffs(b1) - 1;
        else if (b2) first = 64 + __ffs(b2) - 1;
        else if (b3) first = 96 + __ffs(b3) - 1;
        if (b3)      last = 96 + 31 - __clz(b3);
        else if (b2) last = 64 + 31 - __clz(b2);
        else if (b1) last = 32 + 31 - __clz(b1);
        else if (b0) last = 31 - __clz(b0);
    }

    bool valid = false;
    if (tid < L) {
        valid = (tid >= first) && (tid <= last);   // has_data implied by first<=last
        float mn = valid ? v : POS_INF;
        float mx = valid ? v : -POS_INF;
        #pragma unroll
        for (int off = 16; off; off >>= 1) {
            mn = fminf(mn, __shfl_xor_sync(0xffffffffu, mn, off));
            mx = fmaxf(mx, __shfl_xor_sync(0xffffffffu, mx, off));
        }
        if (lane == 0) { smn[warp] = mn; smx[warp] = mx; }
    }
    __syncthreads();

    float xmin = fminf(fminf(smn[0], smn[1]), fminf(smn[2], smn[3]));
    float xmax = fmaxf(fmaxf(smx[0], smx[1]), fmaxf(smx[2], smx[3]));
    // clamp + all-invalid handling collapse into fminf/fmaxf with 0 (inf -> 0)
    xmin = fminf(xmin, 0.0f);
    xmax = fmaxf(xmax, 0.0f);
    float range = fmaxf(xmax - xmin, EPS);

    if (tid < OUT) {
        float xn = valid ? (2.0f * (v - xmin) / range - 1.0f) : 0.0f;
        float c = fminf(fmaxf(xn, -1.0f + EPS), 1.0f - EPS);
        float s = sqrtf(fmaxf(1.0f - c * c, 0.0f));
        scss[tid] = make_float2(c, s);
    }
    __syncthreads();

    // write 65x65 tile: gasf[i][j] = c_i*c_j - s_i*s_j  (== cos(phi_i+phi_j))
    // flat coalesced loop, incremental (i,j): stride 256 = 3*65 + 61
    float* o = out + (size_t)row * OUT2;
    int i = tid / OUT;            // tid < 256 -> i in [0,3], cheap one-time div
    int j = tid - i * OUT;
    #pragma unroll
    for (int it = 0; it < 17; ++it) {
        int idx = tid + it * 256;
        if (idx < OUT2) {                 // only iteration 16 is partial (predicated)
            float2 a = scss[i];           // LDS.64, mostly-broadcast across warp
            float2 b = scss[j];           // LDS.64, lane-stride-1, conflict-free
            o[idx] = fmaf(a.x, b.x, -a.y * b.y);
        }
        i += 3; j += 61;
        if (j >= OUT) { j -= OUT; i += 1; }
    }
}

extern "C" void kernel_launch(void* const* d_in, const int* in_sizes, int n_in,
                              void* d_out, int out_size) {
    const float* x = (const float*)d_in[0];
    float* out = (float*)d_out;
    gasf_kernel<<<N_ROWS, 256>>>(x, out);
}